// round 4
// baseline (speedup 1.0000x reference)
#include <cuda_runtime.h>
#include <math.h>

// ---------------------------------------------------------------------------
// DeformationTrajectoryAttentionBlock — fp32, GEMM-ified stage 2 (per-head).
// B=1, F=4, H=6, D=384, G=16, S=256, N=1024, HD=64, IMG=32, MLP_HID=1536
// ---------------------------------------------------------------------------

#define SCALE 0.125f
#define LN_EPS 1e-5f

#define OFF_TOK    0LL          // 1024*384
#define OFF_XN     393216LL     // 1024*384
#define OFF_QKV    786432LL     // 1024*1152
#define OFF_VW     1966080LL    // 6*1024*768  (viewed as 6144 x 768)
#define OFF_QK     6684672LL    // 6*1024*1024
#define OFF_TA     12976128LL   // 1024*256*24   ta[n][s][h'*4+f]
#define OFF_XD     19267584LL   // 1024*384
#define OFF_Q2     19660800LL   // 1024*384 (pre-scaled)
#define OFF_LG     20054016LL   // 1024*6144  (one head: Lg, then AB in place)
#define OFF_OPART  26345472LL   // 8 splits * 1024*64
#define OFF_O      26869760LL   // 1024*384
#define OFF_H1     27262976LL
#define OFF_HN     27656192LL
#define OFF_MLP    28049408LL   // 1024*1536
#define OFF_H2     29622272LL
#define SCRATCH_FLOATS 30015488LL

static __device__ float g_scratch[SCRATCH_FLOATS];

// ---------------------------------------------------------------------------
// MaxPool2d(2) + rearrange
// ---------------------------------------------------------------------------
__global__ void pool_kernel(const float* __restrict__ x)
{
    float* tok = g_scratch + OFF_TOK;
    int fd = blockIdx.x;
    int f = fd / 384;
    const float* xp = x + (size_t)fd * 1024;
    int t = threadIdx.x;
    int gy = t >> 4, gx = t & 15;
    const float* p = xp + (gy * 2) * 32 + gx * 2;
    float m = fmaxf(fmaxf(p[0], p[1]), fmaxf(p[32], p[33]));
    tok[(size_t)(f * 256 + t) * 384 + (fd % 384)] = m;
}

// ---------------------------------------------------------------------------
// LayerNorm over D=384
// ---------------------------------------------------------------------------
__global__ void ln_kernel(long long inOff, const float* __restrict__ g,
                          const float* __restrict__ b, long long outOff)
{
    const float* in = g_scratch + inOff;
    float* out = g_scratch + outOff;
    int n = blockIdx.x, t = threadIdx.x;
    float x = in[(size_t)n * 384 + t];
    __shared__ float red[12];
    __shared__ float mv[2];
    float s = x;
    #pragma unroll
    for (int o = 16; o; o >>= 1) s += __shfl_xor_sync(0xffffffffu, s, o);
    if ((t & 31) == 0) red[t >> 5] = s;
    __syncthreads();
    if (t == 0) { float tt = 0.f; for (int i = 0; i < 12; i++) tt += red[i]; mv[0] = tt * (1.0f / 384.0f); }
    __syncthreads();
    float mean = mv[0];
    float d = x - mean;
    s = d * d;
    #pragma unroll
    for (int o = 16; o; o >>= 1) s += __shfl_xor_sync(0xffffffffu, s, o);
    if ((t & 31) == 0) red[t >> 5] = s;
    __syncthreads();
    if (t == 0) { float tt = 0.f; for (int i = 0; i < 12; i++) tt += red[i]; mv[1] = rsqrtf(tt * (1.0f / 384.0f) + LN_EPS); }
    __syncthreads();
    out[(size_t)n * 384 + t] = d * mv[1] * g[t] + b[t];
}

// ---------------------------------------------------------------------------
// SGEMM: 128x64x16 tiles, 256 threads, 8x4 microtile, double-buffered smem.
// flags: 1=bias 2=residual 4=gelu 8=B-transposed (NT).
// Batched over z: zb = z % nB selects batch, zk = z / nB selects K-split.
// ---------------------------------------------------------------------------
__global__ void __launch_bounds__(256) gemm_kernel(
    long long aOff, const float* __restrict__ Bp, long long bOff,
    const float* __restrict__ bias, long long rOff, long long cOff,
    int M, int N, int K, int lda, int ldb, int ldc, int ldr,
    long long sA, long long sB, long long sC,
    float alpha, int flags, int nB, int ksplit)
{
    int z = blockIdx.z;
    int zb = z % nB, zk = z / nB;
    int Kloc = K / ksplit;
    const float* A = g_scratch + aOff + (long long)zb * sA + (long long)zk * Kloc;
    const float* Bb = (Bp ? Bp : g_scratch + bOff) + (long long)zb * sB;
    const float* B = Bb + ((flags & 8) ? (long long)zk * Kloc
                                       : (long long)zk * Kloc * ldb);
    float* C = g_scratch + cOff + (long long)z * sC;

    __shared__ __align__(16) float As[2][16][128];
    __shared__ __align__(16) float Bs[2][16][64];

    int bm = blockIdx.y * 128, bn = blockIdx.x * 64;
    int tid = threadIdx.x;
    int a_r = tid >> 1, a_k = (tid & 1) * 8;
    int tx = tid & 15, ty = tid >> 4;

    int nt = Kloc / 16;
    float4 ar0, ar1, br0;

    {
        const float* ap = A + (long long)(bm + a_r) * lda + a_k;
        ar0 = *(const float4*)ap; ar1 = *(const float4*)(ap + 4);
        As[0][a_k + 0][a_r] = ar0.x; As[0][a_k + 1][a_r] = ar0.y;
        As[0][a_k + 2][a_r] = ar0.z; As[0][a_k + 3][a_r] = ar0.w;
        As[0][a_k + 4][a_r] = ar1.x; As[0][a_k + 5][a_r] = ar1.y;
        As[0][a_k + 6][a_r] = ar1.z; As[0][a_k + 7][a_r] = ar1.w;
        if (flags & 8) {
            int r = tid >> 2, k4 = (tid & 3) * 4;
            br0 = *(const float4*)(B + (long long)(bn + r) * ldb + k4);
            Bs[0][k4 + 0][r] = br0.x; Bs[0][k4 + 1][r] = br0.y;
            Bs[0][k4 + 2][r] = br0.z; Bs[0][k4 + 3][r] = br0.w;
        } else {
            int kk = tid >> 4, n4 = (tid & 15) * 4;
            br0 = *(const float4*)(B + (long long)kk * ldb + bn + n4);
            *(float4*)&Bs[0][kk][n4] = br0;
        }
    }
    __syncthreads();

    float acc[8][4];
    #pragma unroll
    for (int i = 0; i < 8; i++)
        #pragma unroll
        for (int j = 0; j < 4; j++) acc[i][j] = 0.f;

    for (int kt = 0; kt < nt; kt++) {
        int cur = kt & 1;
        bool pf = (kt + 1 < nt);
        if (pf) {
            int k0 = (kt + 1) * 16;
            const float* ap = A + (long long)(bm + a_r) * lda + k0 + a_k;
            ar0 = *(const float4*)ap; ar1 = *(const float4*)(ap + 4);
            if (flags & 8) {
                int r = tid >> 2, k4 = (tid & 3) * 4;
                br0 = *(const float4*)(B + (long long)(bn + r) * ldb + k0 + k4);
            } else {
                int kk = tid >> 4, n4 = (tid & 15) * 4;
                br0 = *(const float4*)(B + (long long)(k0 + kk) * ldb + bn + n4);
            }
        }
        #pragma unroll
        for (int kk = 0; kk < 16; kk++) {
            float4 a0 = *(const float4*)&As[cur][kk][ty * 8];
            float4 a1 = *(const float4*)&As[cur][kk][ty * 8 + 4];
            float4 b  = *(const float4*)&Bs[cur][kk][tx * 4];
            acc[0][0] += a0.x * b.x; acc[0][1] += a0.x * b.y; acc[0][2] += a0.x * b.z; acc[0][3] += a0.x * b.w;
            acc[1][0] += a0.y * b.x; acc[1][1] += a0.y * b.y; acc[1][2] += a0.y * b.z; acc[1][3] += a0.y * b.w;
            acc[2][0] += a0.z * b.x; acc[2][1] += a0.z * b.y; acc[2][2] += a0.z * b.z; acc[2][3] += a0.z * b.w;
            acc[3][0] += a0.w * b.x; acc[3][1] += a0.w * b.y; acc[3][2] += a0.w * b.z; acc[3][3] += a0.w * b.w;
            acc[4][0] += a1.x * b.x; acc[4][1] += a1.x * b.y; acc[4][2] += a1.x * b.z; acc[4][3] += a1.x * b.w;
            acc[5][0] += a1.y * b.x; acc[5][1] += a1.y * b.y; acc[5][2] += a1.y * b.z; acc[5][3] += a1.y * b.w;
            acc[6][0] += a1.z * b.x; acc[6][1] += a1.z * b.y; acc[6][2] += a1.z * b.z; acc[6][3] += a1.z * b.w;
            acc[7][0] += a1.w * b.x; acc[7][1] += a1.w * b.y; acc[7][2] += a1.w * b.z; acc[7][3] += a1.w * b.w;
        }
        if (pf) {
            int nx = 1 - cur;
            As[nx][a_k + 0][a_r] = ar0.x; As[nx][a_k + 1][a_r] = ar0.y;
            As[nx][a_k + 2][a_r] = ar0.z; As[nx][a_k + 3][a_r] = ar0.w;
            As[nx][a_k + 4][a_r] = ar1.x; As[nx][a_k + 5][a_r] = ar1.y;
            As[nx][a_k + 6][a_r] = ar1.z; As[nx][a_k + 7][a_r] = ar1.w;
            if (flags & 8) {
                int r = tid >> 2, k4 = (tid & 3) * 4;
                Bs[nx][k4 + 0][r] = br0.x; Bs[nx][k4 + 1][r] = br0.y;
                Bs[nx][k4 + 2][r] = br0.z; Bs[nx][k4 + 3][r] = br0.w;
            } else {
                int kk = tid >> 4, n4 = (tid & 15) * 4;
                *(float4*)&Bs[nx][kk][n4] = br0;
            }
            __syncthreads();
        }
    }

    int row0 = bm + ty * 8, col0 = bn + tx * 4;
    const float* R = g_scratch + rOff;
    #pragma unroll
    for (int i = 0; i < 8; i++) {
        #pragma unroll
        for (int j = 0; j < 4; j++) {
            float v = alpha * acc[i][j];
            if (flags & 1) v += bias[col0 + j];
            if (flags & 4) v = 0.5f * v * (1.0f + erff(v * 0.7071067811865476f));
            if (flags & 2) v += R[(long long)(row0 + i) * ldr + col0 + j];
            C[(long long)(row0 + i) * ldc + col0 + j] = v;
        }
    }
}

// ---------------------------------------------------------------------------
// time_attn softmax over F=4
// ---------------------------------------------------------------------------
__global__ void ta_kernel()
{
    const float* qk = g_scratch + OFF_QK;
    float* ta = g_scratch + OFF_TA;
    int b = blockIdx.x;
    int h = b >> 10, n = b & 1023;
    int s = threadIdx.x;
    const float* p = qk + ((size_t)b << 10) + s;
    float x0 = SCALE * p[0], x1 = SCALE * p[256], x2 = SCALE * p[512], x3 = SCALE * p[768];
    float m = fmaxf(fmaxf(x0, x1), fmaxf(x2, x3));
    float e0 = expf(x0 - m), e1 = expf(x1 - m), e2 = expf(x2 - m), e3 = expf(x3 - m);
    float inv = 1.0f / (e0 + e1 + e2 + e3);
    float* o = ta + ((size_t)(n * 256 + s)) * 24 + h * 4;
    o[0] = e0 * inv; o[1] = e1 * inv; o[2] = e2 * inv; o[3] = e3 * inv;
}

// ---------------------------------------------------------------------------
// x_diag
// ---------------------------------------------------------------------------
__global__ void xdiag_kernel()
{
    const float* ta = g_scratch + OFF_TA;
    const float* qkv = g_scratch + OFF_QKV;
    float* xd = g_scratch + OFF_XD;
    int n = blockIdx.x, c = threadIdx.x;
    int h = c >> 6;
    int s = n & 255;
    const float* tp = ta + ((size_t)(n * 256 + s)) * 24 + h * 4;
    float acc = 0.f;
    #pragma unroll
    for (int f = 0; f < 4; f++)
        acc += tp[f] * qkv[(size_t)(f * 256 + s) * 1152 + 768 + c];
    xd[(size_t)n * 384 + c] = acc;
}

// ---------------------------------------------------------------------------
// middle (per head h): logits contraction + softmax + AB in place + attn out
// block = n (1024), threads = s (256)
// ---------------------------------------------------------------------------
__global__ void __launch_bounds__(256) middle_kernel(int h, float* __restrict__ out_attn,
                                                     int write_out)
{
    int n = blockIdx.x;
    int s = threadIdx.x;
    __shared__ __align__(16) float sta[256][24];
    __shared__ float red[8];
    __shared__ float mv[2];

    const float4* tap = (const float4*)(g_scratch + OFF_TA + (size_t)n * 6144);
    float4* stp = (float4*)&sta[0][0];
    for (int idx = s; idx < 1536; idx += 256)
        stp[idx] = tap[idx];
    __syncthreads();

    float* lg = g_scratch + OFF_LG + (size_t)n * 6144;
    float logit = 0.f;
    #pragma unroll
    for (int j = 0; j < 24; j++)
        logit += sta[s][j] * lg[j * 256 + s];

    float m = logit;
    #pragma unroll
    for (int o = 16; o; o >>= 1) m = fmaxf(m, __shfl_xor_sync(0xffffffffu, m, o));
    if ((s & 31) == 0) red[s >> 5] = m;
    __syncthreads();
    if (s == 0) { float t = red[0]; for (int i = 1; i < 8; i++) t = fmaxf(t, red[i]); mv[0] = t; }
    __syncthreads();
    float e = expf(logit - mv[0]);
    float sum = e;
    #pragma unroll
    for (int o = 16; o; o >>= 1) sum += __shfl_xor_sync(0xffffffffu, sum, o);
    if ((s & 31) == 0) red[s >> 5] = sum;
    __syncthreads();
    if (s == 0) { float t = 0.f; for (int i = 0; i < 8; i++) t += red[i]; mv[1] = 1.0f / t; }
    __syncthreads();
    float sa = e * mv[1];
    if (write_out) out_attn[((size_t)h * 1024 + n) * 256 + s] = sa;
    #pragma unroll
    for (int j = 0; j < 24; j++)
        lg[j * 256 + s] = sa * sta[s][j];
}

// ---------------------------------------------------------------------------
// per-head split-K reduce: O[n][h*64+c] = sum_zk opart[zk][n][c]
// ---------------------------------------------------------------------------
__global__ void oreduce_kernel(int h)
{
    const float* opart = g_scratch + OFF_OPART;
    float* o = g_scratch + OFF_O;
    int i = blockIdx.x * 256 + threadIdx.x;       // < 1024*64
    float sum = 0.f;
    #pragma unroll
    for (int zk = 0; zk < 8; zk++)
        sum += opart[(size_t)zk * 65536 + i];
    o[(size_t)(i >> 6) * 384 + h * 64 + (i & 63)] = sum;
}

// ---------------------------------------------------------------------------
// bilinear 16->32 upsample
// ---------------------------------------------------------------------------
__global__ void upsample_kernel(float* __restrict__ out, int out_size)
{
    const float* h2 = g_scratch + OFF_H2;
    int fd = blockIdx.x;
    int f = fd / 384, d = fd % 384;
    __shared__ float ch[256];
    int t = threadIdx.x;
    ch[t] = h2[(size_t)(f * 256 + t) * 384 + d];
    __syncthreads();
    #pragma unroll
    for (int p = 0; p < 4; p++) {
        int o = t + p * 256;
        int oy = o >> 5, ox = o & 31;
        float fy = 0.5f * oy - 0.25f;
        int iy0 = (int)floorf(fy);
        float wy = fy - (float)iy0;
        int iy0c = max(iy0, 0), iy1c = min(iy0 + 1, 15);
        float fx = 0.5f * ox - 0.25f;
        int ix0 = (int)floorf(fx);
        float wx = fx - (float)ix0;
        int ix0c = max(ix0, 0), ix1c = min(ix0 + 1, 15);
        float v00 = ch[iy0c * 16 + ix0c], v01 = ch[iy0c * 16 + ix1c];
        float v10 = ch[iy1c * 16 + ix0c], v11 = ch[iy1c * 16 + ix1c];
        float v = (1.f - wy) * ((1.f - wx) * v00 + wx * v01)
                + wy * ((1.f - wx) * v10 + wx * v11);
        long long oi = (long long)fd * 1024 + o;
        if (oi < (long long)out_size) out[oi] = v;
    }
}

// ---------------------------------------------------------------------------
extern "C" void kernel_launch(void* const* d_in, const int* in_sizes, int n_in,
                              void* d_out, int out_size)
{
    (void)in_sizes; (void)n_in;
    const float* x      = (const float*)d_in[0];
    const float* qkv_w  = (const float*)d_in[1];
    const float* q2_w   = (const float*)d_in[2];
    const float* kv2_w  = (const float*)d_in[3];
    const float* proj_w = (const float*)d_in[4];
    const float* proj_b = (const float*)d_in[5];
    const float* ln1_g  = (const float*)d_in[6];
    const float* ln1_b  = (const float*)d_in[7];
    const float* ln2_g  = (const float*)d_in[8];
    const float* ln2_b  = (const float*)d_in[9];
    const float* fc1_w  = (const float*)d_in[10];
    const float* fc1_b  = (const float*)d_in[11];
    const float* fc2_w  = (const float*)d_in[12];
    const float* fc2_b  = (const float*)d_in[13];
    float* out = (float*)d_out;

    pool_kernel<<<1536, 256>>>(x);
    ln_kernel<<<1024, 384>>>(OFF_TOK, ln1_g, ln1_b, OFF_XN);

    // qkv = xn @ qkv_w
    gemm_kernel<<<dim3(18, 8, 1), 256>>>(OFF_XN, qkv_w, 0, nullptr, 0, OFF_QKV,
        1024, 1152, 384, 384, 1152, 1152, 0, 0, 0, 0, 1.0f, 0, 1, 1);

    // VW[h'] = v_h' @ kv2_w[h' slice]   (6 batched NN, K=64)
    gemm_kernel<<<dim3(12, 8, 6), 256>>>(OFF_QKV + 768, kv2_w, 0, nullptr, 0, OFF_VW,
        1024, 768, 64, 1152, 768, 768, 0, 64, 49152, 786432, 1.0f, 0, 6, 1);

    // qk[h] = q_h @ k_h^T   (6 batched NT)
    gemm_kernel<<<dim3(16, 8, 6), 256>>>(OFF_QKV, nullptr, OFF_QKV + 384, nullptr, 0, OFF_QK,
        1024, 1024, 64, 1152, 1152, 1024, 0, 64, 64, 1048576, 1.0f, 8, 6, 1);

    ta_kernel<<<6144, 256>>>();
    xdiag_kernel<<<1024, 384>>>();

    // q2 = SCALE * x_diag @ q2_w
    gemm_kernel<<<dim3(6, 8, 1), 256>>>(OFF_XD, q2_w, 0, nullptr, 0, OFF_Q2,
        1024, 384, 384, 384, 384, 384, 0, 0, 0, 0, SCALE, 0, 1, 1);

    int wout = (out_size >= 3145728) ? 1 : 0;

    // stage 2, per head: Lg GEMM -> middle -> o GEMM (split-K 8) -> reduce
    for (int h = 0; h < 6; h++) {
        // Lg = q2_h @ VWall[:, h*64:+64]^T   (1024 x 6144 x 64, NT)
        gemm_kernel<<<dim3(96, 8, 1), 256>>>(OFF_Q2 + h * 64, nullptr, OFF_VW + h * 64,
            nullptr, 0, OFF_LG,
            1024, 6144, 64, 384, 768, 6144, 0, 0, 0, 0, 1.0f, 8, 1, 1);

        middle_kernel<<<1024, 256>>>(h, out + 1572864, wout);

        // o_h partials = AB @ VWall[:, 384+h*64:+64]  (1024 x 64 x 6144, split-K 8)
        gemm_kernel<<<dim3(1, 8, 8), 256>>>(OFF_LG, nullptr, OFF_VW + 384 + h * 64,
            nullptr, 0, OFF_OPART,
            1024, 64, 6144, 6144, 768, 64, 0, 0, 0, 65536, 1.0f, 0, 1, 8);

        oreduce_kernel<<<256, 256>>>(h);
    }

    // h1 = tok + (o @ proj_w + proj_b)
    gemm_kernel<<<dim3(6, 8, 1), 256>>>(OFF_O, proj_w, 0, proj_b, OFF_TOK, OFF_H1,
        1024, 384, 384, 384, 384, 384, 384, 0, 0, 0, 1.0f, 1 | 2, 1, 1);

    ln_kernel<<<1024, 384>>>(OFF_H1, ln2_g, ln2_b, OFF_HN);

    // mlp
    gemm_kernel<<<dim3(24, 8, 1), 256>>>(OFF_HN, fc1_w, 0, fc1_b, 0, OFF_MLP,
        1024, 1536, 384, 384, 1536, 1536, 0, 0, 0, 0, 1.0f, 1 | 4, 1, 1);
    gemm_kernel<<<dim3(6, 8, 1), 256>>>(OFF_MLP, fc2_w, 0, fc2_b, OFF_H1, OFF_H2,
        1024, 384, 1536, 1536, 384, 384, 384, 0, 0, 0, 1.0f, 1 | 2, 1, 1);

    upsample_kernel<<<1536, 256>>>(out, out_size);
}

// round 5
// speedup vs baseline: 1.1159x; 1.1159x over previous
#include <cuda_runtime.h>
#include <math.h>

// ---------------------------------------------------------------------------
// DeformationTrajectoryAttentionBlock — fp32; GEMM-ified stage 2, grouped x2.
// B=1, F=4, H=6, D=384, G=16, S=256, N=1024, HD=64, IMG=32, MLP_HID=1536
// ---------------------------------------------------------------------------

#define SCALE 0.125f
#define LN_EPS 1e-5f

#define OFF_TOK    0LL          // 1024*384
#define OFF_XN     393216LL
#define OFF_QKV    786432LL     // 1024*1152
#define OFF_VW     1966080LL    // 6*1024*768 (6144 x 768)
#define OFF_QK     6684672LL    // 6*1024*1024 ; reused as Lg[hg=0] after ta
#define OFF_TA     12976128LL   // 1024*256*24
#define OFF_XD     19267584LL
#define OFF_Q2     19660800LL
#define OFF_LG     20054016LL   // 1024*6144 ; Lg[hg=1]
#define LG_STRIDE  13369344LL   // OFF_LG - OFF_QK
#define OFF_OPART  26345472LL   // 24 * 1024*64
#define OFF_O      27918336LL
#define OFF_H1     28311552LL
#define OFF_HN     28704768LL
#define OFF_MLP    29097984LL   // 1024*1536
#define OFF_H2     30670848LL
#define SCRATCH_FLOATS 31064064LL

static __device__ float g_scratch[SCRATCH_FLOATS];

// ---------------------------------------------------------------------------
__global__ void pool_kernel(const float* __restrict__ x)
{
    float* tok = g_scratch + OFF_TOK;
    int fd = blockIdx.x;
    int f = fd / 384;
    const float* xp = x + (size_t)fd * 1024;
    int t = threadIdx.x;
    int gy = t >> 4, gx = t & 15;
    const float* p = xp + (gy * 2) * 32 + gx * 2;
    float m = fmaxf(fmaxf(p[0], p[1]), fmaxf(p[32], p[33]));
    tok[(size_t)(f * 256 + t) * 384 + (fd % 384)] = m;
}

// ---------------------------------------------------------------------------
__global__ void ln_kernel(long long inOff, const float* __restrict__ g,
                          const float* __restrict__ b, long long outOff)
{
    const float* in = g_scratch + inOff;
    float* out = g_scratch + outOff;
    int n = blockIdx.x, t = threadIdx.x;
    float x = in[(size_t)n * 384 + t];
    __shared__ float red[12];
    __shared__ float mv[2];
    float s = x;
    #pragma unroll
    for (int o = 16; o; o >>= 1) s += __shfl_xor_sync(0xffffffffu, s, o);
    if ((t & 31) == 0) red[t >> 5] = s;
    __syncthreads();
    if (t == 0) { float tt = 0.f; for (int i = 0; i < 12; i++) tt += red[i]; mv[0] = tt * (1.0f / 384.0f); }
    __syncthreads();
    float mean = mv[0];
    float d = x - mean;
    s = d * d;
    #pragma unroll
    for (int o = 16; o; o >>= 1) s += __shfl_xor_sync(0xffffffffu, s, o);
    if ((t & 31) == 0) red[t >> 5] = s;
    __syncthreads();
    if (t == 0) { float tt = 0.f; for (int i = 0; i < 12; i++) tt += red[i]; mv[1] = rsqrtf(tt * (1.0f / 384.0f) + LN_EPS); }
    __syncthreads();
    out[(size_t)n * 384 + t] = d * mv[1] * g[t] + b[t];
}

// ---------------------------------------------------------------------------
// gemm128: 128x128x16 tiles, 256 threads, 8x8 microtile, double-buffered.
// flags: 1=bias 4=gelu 8=NT. M rows = blockIdx.y*128 (M=1024 assumed mult 128).
// ---------------------------------------------------------------------------
__global__ void __launch_bounds__(256) gemm128_kernel(
    long long aOff, const float* __restrict__ Bp, long long bOff,
    const float* __restrict__ bias, long long cOff,
    int K, int lda, int ldb, int ldc,
    long long sA, long long sB, long long sC,
    float alpha, int flags)
{
    int z = blockIdx.z;
    const float* A = g_scratch + aOff + (long long)z * sA;
    const float* B = (Bp ? Bp : g_scratch + bOff) + (long long)z * sB;
    float* C = g_scratch + cOff + (long long)z * sC;

    __shared__ __align__(16) float As[2][16][128];
    __shared__ __align__(16) float Bs[2][16][128];

    int bm = blockIdx.y * 128, bn = blockIdx.x * 128;
    int tid = threadIdx.x;
    int r2 = tid >> 1, k8 = (tid & 1) * 8;   // A / NT-B loader
    int bk = tid >> 4, c8 = (tid & 15) * 8;  // NN-B loader
    int ty = tid >> 4, tx = tid & 15;

    int nt = K / 16;
    float4 ar0, ar1, br0, br1;

    {
        const float* ap = A + (long long)(bm + r2) * lda + k8;
        ar0 = *(const float4*)ap; ar1 = *(const float4*)(ap + 4);
        As[0][k8 + 0][r2] = ar0.x; As[0][k8 + 1][r2] = ar0.y;
        As[0][k8 + 2][r2] = ar0.z; As[0][k8 + 3][r2] = ar0.w;
        As[0][k8 + 4][r2] = ar1.x; As[0][k8 + 5][r2] = ar1.y;
        As[0][k8 + 6][r2] = ar1.z; As[0][k8 + 7][r2] = ar1.w;
        if (flags & 8) {
            const float* bp = B + (long long)(bn + r2) * ldb + k8;
            br0 = *(const float4*)bp; br1 = *(const float4*)(bp + 4);
            Bs[0][k8 + 0][r2] = br0.x; Bs[0][k8 + 1][r2] = br0.y;
            Bs[0][k8 + 2][r2] = br0.z; Bs[0][k8 + 3][r2] = br0.w;
            Bs[0][k8 + 4][r2] = br1.x; Bs[0][k8 + 5][r2] = br1.y;
            Bs[0][k8 + 6][r2] = br1.z; Bs[0][k8 + 7][r2] = br1.w;
        } else {
            const float* bp = B + (long long)bk * ldb + bn + c8;
            br0 = *(const float4*)bp; br1 = *(const float4*)(bp + 4);
            *(float4*)&Bs[0][bk][c8] = br0;
            *(float4*)&Bs[0][bk][c8 + 4] = br1;
        }
    }
    __syncthreads();

    float acc[8][8];
    #pragma unroll
    for (int i = 0; i < 8; i++)
        #pragma unroll
        for (int j = 0; j < 8; j++) acc[i][j] = 0.f;

    for (int kt = 0; kt < nt; kt++) {
        int cur = kt & 1;
        bool pf = (kt + 1 < nt);
        if (pf) {
            int k0 = (kt + 1) * 16;
            const float* ap = A + (long long)(bm + r2) * lda + k0 + k8;
            ar0 = *(const float4*)ap; ar1 = *(const float4*)(ap + 4);
            if (flags & 8) {
                const float* bp = B + (long long)(bn + r2) * ldb + k0 + k8;
                br0 = *(const float4*)bp; br1 = *(const float4*)(bp + 4);
            } else {
                const float* bp = B + (long long)(k0 + bk) * ldb + bn + c8;
                br0 = *(const float4*)bp; br1 = *(const float4*)(bp + 4);
            }
        }
        #pragma unroll
        for (int kk = 0; kk < 16; kk++) {
            float a[8], b[8];
            *(float4*)&a[0] = *(const float4*)&As[cur][kk][ty * 8];
            *(float4*)&a[4] = *(const float4*)&As[cur][kk][ty * 8 + 4];
            *(float4*)&b[0] = *(const float4*)&Bs[cur][kk][tx * 8];
            *(float4*)&b[4] = *(const float4*)&Bs[cur][kk][tx * 8 + 4];
            #pragma unroll
            for (int i = 0; i < 8; i++)
                #pragma unroll
                for (int j = 0; j < 8; j++)
                    acc[i][j] += a[i] * b[j];
        }
        if (pf) {
            int nx = 1 - cur;
            As[nx][k8 + 0][r2] = ar0.x; As[nx][k8 + 1][r2] = ar0.y;
            As[nx][k8 + 2][r2] = ar0.z; As[nx][k8 + 3][r2] = ar0.w;
            As[nx][k8 + 4][r2] = ar1.x; As[nx][k8 + 5][r2] = ar1.y;
            As[nx][k8 + 6][r2] = ar1.z; As[nx][k8 + 7][r2] = ar1.w;
            if (flags & 8) {
                Bs[nx][k8 + 0][r2] = br0.x; Bs[nx][k8 + 1][r2] = br0.y;
                Bs[nx][k8 + 2][r2] = br0.z; Bs[nx][k8 + 3][r2] = br0.w;
                Bs[nx][k8 + 4][r2] = br1.x; Bs[nx][k8 + 5][r2] = br1.y;
                Bs[nx][k8 + 6][r2] = br1.z; Bs[nx][k8 + 7][r2] = br1.w;
            } else {
                *(float4*)&Bs[nx][bk][c8] = br0;
                *(float4*)&Bs[nx][bk][c8 + 4] = br1;
            }
            __syncthreads();
        }
    }

    int row0 = bm + ty * 8, col0 = bn + tx * 8;
    #pragma unroll
    for (int i = 0; i < 8; i++) {
        float v[8];
        #pragma unroll
        for (int j = 0; j < 8; j++) {
            float t = alpha * acc[i][j];
            if (flags & 1) t += bias[col0 + j];
            if (flags & 4) t = 0.5f * t * (1.0f + erff(t * 0.7071067811865476f));
            v[j] = t;
        }
        float* cp = C + (long long)(row0 + i) * ldc + col0;
        *(float4*)cp = *(float4*)&v[0];
        *(float4*)(cp + 4) = *(float4*)&v[4];
    }
}

// ---------------------------------------------------------------------------
// gemm64: 128x64x16 tiles (R4-proven). flags: 1=bias 2=residual 4=gelu 8=NT.
// z: zb = z%nB batch, zk = z/nB K-split.
// ---------------------------------------------------------------------------
__global__ void __launch_bounds__(256) gemm64_kernel(
    long long aOff, const float* __restrict__ Bp, long long bOff,
    const float* __restrict__ bias, long long rOff, long long cOff,
    int M, int N, int K, int lda, int ldb, int ldc, int ldr,
    long long sA, long long sB, long long sC,
    float alpha, int flags, int nB, int ksplit)
{
    int z = blockIdx.z;
    int zb = z % nB, zk = z / nB;
    int Kloc = K / ksplit;
    const float* A = g_scratch + aOff + (long long)zb * sA + (long long)zk * Kloc;
    const float* Bb = (Bp ? Bp : g_scratch + bOff) + (long long)zb * sB;
    const float* B = Bb + ((flags & 8) ? (long long)zk * Kloc
                                       : (long long)zk * Kloc * ldb);
    float* C = g_scratch + cOff + (long long)z * sC;

    __shared__ __align__(16) float As[2][16][128];
    __shared__ __align__(16) float Bs[2][16][64];

    int bm = blockIdx.y * 128, bn = blockIdx.x * 64;
    int tid = threadIdx.x;
    int a_r = tid >> 1, a_k = (tid & 1) * 8;
    int tx = tid & 15, ty = tid >> 4;

    int nt = Kloc / 16;
    float4 ar0, ar1, br0;

    {
        const float* ap = A + (long long)(bm + a_r) * lda + a_k;
        ar0 = *(const float4*)ap; ar1 = *(const float4*)(ap + 4);
        As[0][a_k + 0][a_r] = ar0.x; As[0][a_k + 1][a_r] = ar0.y;
        As[0][a_k + 2][a_r] = ar0.z; As[0][a_k + 3][a_r] = ar0.w;
        As[0][a_k + 4][a_r] = ar1.x; As[0][a_k + 5][a_r] = ar1.y;
        As[0][a_k + 6][a_r] = ar1.z; As[0][a_k + 7][a_r] = ar1.w;
        if (flags & 8) {
            int r = tid >> 2, k4 = (tid & 3) * 4;
            br0 = *(const float4*)(B + (long long)(bn + r) * ldb + k4);
            Bs[0][k4 + 0][r] = br0.x; Bs[0][k4 + 1][r] = br0.y;
            Bs[0][k4 + 2][r] = br0.z; Bs[0][k4 + 3][r] = br0.w;
        } else {
            int kk = tid >> 4, n4 = (tid & 15) * 4;
            br0 = *(const float4*)(B + (long long)kk * ldb + bn + n4);
            *(float4*)&Bs[0][kk][n4] = br0;
        }
    }
    __syncthreads();

    float acc[8][4];
    #pragma unroll
    for (int i = 0; i < 8; i++)
        #pragma unroll
        for (int j = 0; j < 4; j++) acc[i][j] = 0.f;

    for (int kt = 0; kt < nt; kt++) {
        int cur = kt & 1;
        bool pf = (kt + 1 < nt);
        if (pf) {
            int k0 = (kt + 1) * 16;
            const float* ap = A + (long long)(bm + a_r) * lda + k0 + a_k;
            ar0 = *(const float4*)ap; ar1 = *(const float4*)(ap + 4);
            if (flags & 8) {
                int r = tid >> 2, k4 = (tid & 3) * 4;
                br0 = *(const float4*)(B + (long long)(bn + r) * ldb + k0 + k4);
            } else {
                int kk = tid >> 4, n4 = (tid & 15) * 4;
                br0 = *(const float4*)(B + (long long)(k0 + kk) * ldb + bn + n4);
            }
        }
        #pragma unroll
        for (int kk = 0; kk < 16; kk++) {
            float4 a0 = *(const float4*)&As[cur][kk][ty * 8];
            float4 a1 = *(const float4*)&As[cur][kk][ty * 8 + 4];
            float4 b  = *(const float4*)&Bs[cur][kk][tx * 4];
            acc[0][0] += a0.x * b.x; acc[0][1] += a0.x * b.y; acc[0][2] += a0.x * b.z; acc[0][3] += a0.x * b.w;
            acc[1][0] += a0.y * b.x; acc[1][1] += a0.y * b.y; acc[1][2] += a0.y * b.z; acc[1][3] += a0.y * b.w;
            acc[2][0] += a0.z * b.x; acc[2][1] += a0.z * b.y; acc[2][2] += a0.z * b.z; acc[2][3] += a0.z * b.w;
            acc[3][0] += a0.w * b.x; acc[3][1] += a0.w * b.y; acc[3][2] += a0.w * b.z; acc[3][3] += a0.w * b.w;
            acc[4][0] += a1.x * b.x; acc[4][1] += a1.x * b.y; acc[4][2] += a1.x * b.z; acc[4][3] += a1.x * b.w;
            acc[5][0] += a1.y * b.x; acc[5][1] += a1.y * b.y; acc[5][2] += a1.y * b.z; acc[5][3] += a1.y * b.w;
            acc[6][0] += a1.z * b.x; acc[6][1] += a1.z * b.y; acc[6][2] += a1.z * b.z; acc[6][3] += a1.z * b.w;
            acc[7][0] += a1.w * b.x; acc[7][1] += a1.w * b.y; acc[7][2] += a1.w * b.z; acc[7][3] += a1.w * b.w;
        }
        if (pf) {
            int nx = 1 - cur;
            As[nx][a_k + 0][a_r] = ar0.x; As[nx][a_k + 1][a_r] = ar0.y;
            As[nx][a_k + 2][a_r] = ar0.z; As[nx][a_k + 3][a_r] = ar0.w;
            As[nx][a_k + 4][a_r] = ar1.x; As[nx][a_k + 5][a_r] = ar1.y;
            As[nx][a_k + 6][a_r] = ar1.z; As[nx][a_k + 7][a_r] = ar1.w;
            if (flags & 8) {
                int r = tid >> 2, k4 = (tid & 3) * 4;
                Bs[nx][k4 + 0][r] = br0.x; Bs[nx][k4 + 1][r] = br0.y;
                Bs[nx][k4 + 2][r] = br0.z; Bs[nx][k4 + 3][r] = br0.w;
            } else {
                int kk = tid >> 4, n4 = (tid & 15) * 4;
                *(float4*)&Bs[nx][kk][n4] = br0;
            }
            __syncthreads();
        }
    }

    int row0 = bm + ty * 8, col0 = bn + tx * 4;
    const float* R = g_scratch + rOff;
    #pragma unroll
    for (int i = 0; i < 8; i++) {
        #pragma unroll
        for (int j = 0; j < 4; j++) {
            float v = alpha * acc[i][j];
            if (flags & 1) v += bias[col0 + j];
            if (flags & 4) v = 0.5f * v * (1.0f + erff(v * 0.7071067811865476f));
            if (flags & 2) v += R[(long long)(row0 + i) * ldr + col0 + j];
            C[(long long)(row0 + i) * ldc + col0 + j] = v;
        }
    }
}

// ---------------------------------------------------------------------------
__global__ void ta_kernel()
{
    const float* qk = g_scratch + OFF_QK;
    float* ta = g_scratch + OFF_TA;
    int b = blockIdx.x;
    int h = b >> 10, n = b & 1023;
    int s = threadIdx.x;
    const float* p = qk + ((size_t)b << 10) + s;
    float x0 = SCALE * p[0], x1 = SCALE * p[256], x2 = SCALE * p[512], x3 = SCALE * p[768];
    float m = fmaxf(fmaxf(x0, x1), fmaxf(x2, x3));
    float e0 = expf(x0 - m), e1 = expf(x1 - m), e2 = expf(x2 - m), e3 = expf(x3 - m);
    float inv = 1.0f / (e0 + e1 + e2 + e3);
    float* o = ta + ((size_t)(n * 256 + s)) * 24 + h * 4;
    o[0] = e0 * inv; o[1] = e1 * inv; o[2] = e2 * inv; o[3] = e3 * inv;
}

// ---------------------------------------------------------------------------
__global__ void xdiag_kernel()
{
    const float* ta = g_scratch + OFF_TA;
    const float* qkv = g_scratch + OFF_QKV;
    float* xd = g_scratch + OFF_XD;
    int n = blockIdx.x, c = threadIdx.x;
    int h = c >> 6;
    int s = n & 255;
    const float* tp = ta + ((size_t)(n * 256 + s)) * 24 + h * 4;
    float acc = 0.f;
    #pragma unroll
    for (int f = 0; f < 4; f++)
        acc += tp[f] * qkv[(size_t)(f * 256 + s) * 1152 + 768 + c];
    xd[(size_t)n * 384 + c] = acc;
}

// ---------------------------------------------------------------------------
// middle (head group g, hg = blockIdx.y): logits + softmax + AB in place
// ---------------------------------------------------------------------------
__global__ void __launch_bounds__(256) middle_kernel(int g, float* __restrict__ out_attn,
                                                     int write_out)
{
    int n = blockIdx.x;
    int hg = blockIdx.y;
    int s = threadIdx.x;
    __shared__ __align__(16) float sta[256][24];
    __shared__ float red[8];
    __shared__ float mv[2];

    const float4* tap = (const float4*)(g_scratch + OFF_TA + (size_t)n * 6144);
    float4* stp = (float4*)&sta[0][0];
    for (int idx = s; idx < 1536; idx += 256)
        stp[idx] = tap[idx];
    __syncthreads();

    float* lg = g_scratch + OFF_QK + (long long)hg * LG_STRIDE + (size_t)n * 6144;
    float logit = 0.f;
    #pragma unroll
    for (int j = 0; j < 24; j++)
        logit += sta[s][j] * lg[j * 256 + s];

    float m = logit;
    #pragma unroll
    for (int o = 16; o; o >>= 1) m = fmaxf(m, __shfl_xor_sync(0xffffffffu, m, o));
    if ((s & 31) == 0) red[s >> 5] = m;
    __syncthreads();
    if (s == 0) { float t = red[0]; for (int i = 1; i < 8; i++) t = fmaxf(t, red[i]); mv[0] = t; }
    __syncthreads();
    float e = expf(logit - mv[0]);
    float sum = e;
    #pragma unroll
    for (int o = 16; o; o >>= 1) sum += __shfl_xor_sync(0xffffffffu, sum, o);
    if ((s & 31) == 0) red[s >> 5] = sum;
    __syncthreads();
    if (s == 0) { float t = 0.f; for (int i = 0; i < 8; i++) t += red[i]; mv[1] = 1.0f / t; }
    __syncthreads();
    float sa = e * mv[1];
    if (write_out) out_attn[((size_t)(g * 2 + hg) * 1024 + n) * 256 + s] = sa;
    #pragma unroll
    for (int j = 0; j < 24; j++)
        lg[j * 256 + s] = sa * sta[s][j];
}

// ---------------------------------------------------------------------------
// split-K(12) reduce for head group g: covers 2 heads * 1024*64
// ---------------------------------------------------------------------------
__global__ void oreduce_kernel(int g)
{
    const float* opart = g_scratch + OFF_OPART;
    float* o = g_scratch + OFF_O;
    int i = blockIdx.x * 256 + threadIdx.x;       // < 131072
    int hg = i >> 16;
    int r = i & 65535;
    float sum = 0.f;
    #pragma unroll
    for (int zk = 0; zk < 12; zk++)
        sum += opart[(size_t)(zk * 2 + hg) * 65536 + r];
    o[(size_t)(r >> 6) * 384 + (g * 2 + hg) * 64 + (r & 63)] = sum;
}

// ---------------------------------------------------------------------------
__global__ void upsample_kernel(float* __restrict__ out, int out_size)
{
    const float* h2 = g_scratch + OFF_H2;
    int fd = blockIdx.x;
    int f = fd / 384, d = fd % 384;
    __shared__ float ch[256];
    int t = threadIdx.x;
    ch[t] = h2[(size_t)(f * 256 + t) * 384 + d];
    __syncthreads();
    #pragma unroll
    for (int p = 0; p < 4; p++) {
        int o = t + p * 256;
        int oy = o >> 5, ox = o & 31;
        float fy = 0.5f * oy - 0.25f;
        int iy0 = (int)floorf(fy);
        float wy = fy - (float)iy0;
        int iy0c = max(iy0, 0), iy1c = min(iy0 + 1, 15);
        float fx = 0.5f * ox - 0.25f;
        int ix0 = (int)floorf(fx);
        float wx = fx - (float)ix0;
        int ix0c = max(ix0, 0), ix1c = min(ix0 + 1, 15);
        float v00 = ch[iy0c * 16 + ix0c], v01 = ch[iy0c * 16 + ix1c];
        float v10 = ch[iy1c * 16 + ix0c], v11 = ch[iy1c * 16 + ix1c];
        float v = (1.f - wy) * ((1.f - wx) * v00 + wx * v01)
                + wy * ((1.f - wx) * v10 + wx * v11);
        long long oi = (long long)fd * 1024 + o;
        if (oi < (long long)out_size) out[oi] = v;
    }
}

// ---------------------------------------------------------------------------
extern "C" void kernel_launch(void* const* d_in, const int* in_sizes, int n_in,
                              void* d_out, int out_size)
{
    (void)in_sizes; (void)n_in;
    const float* x      = (const float*)d_in[0];
    const float* qkv_w  = (const float*)d_in[1];
    const float* q2_w   = (const float*)d_in[2];
    const float* kv2_w  = (const float*)d_in[3];
    const float* proj_w = (const float*)d_in[4];
    const float* proj_b = (const float*)d_in[5];
    const float* ln1_g  = (const float*)d_in[6];
    const float* ln1_b  = (const float*)d_in[7];
    const float* ln2_g  = (const float*)d_in[8];
    const float* ln2_b  = (const float*)d_in[9];
    const float* fc1_w  = (const float*)d_in[10];
    const float* fc1_b  = (const float*)d_in[11];
    const float* fc2_w  = (const float*)d_in[12];
    const float* fc2_b  = (const float*)d_in[13];
    float* out = (float*)d_out;

    pool_kernel<<<1536, 256>>>(x);
    ln_kernel<<<1024, 384>>>(OFF_TOK, ln1_g, ln1_b, OFF_XN);

    // qkv = xn @ qkv_w   (1024 x 1152 x 384, NN)
    gemm128_kernel<<<dim3(9, 8, 1), 256>>>(OFF_XN, qkv_w, 0, nullptr, OFF_QKV,
        384, 384, 1152, 1152, 0, 0, 0, 1.0f, 0);

    // VW[h'] = v_h' @ kv2_w[h' slice]   (6 batched NN, K=64)
    gemm128_kernel<<<dim3(6, 8, 6), 256>>>(OFF_QKV + 768, kv2_w, 0, nullptr, OFF_VW,
        64, 1152, 768, 768, 64, 49152, 786432, 1.0f, 0);

    // qk[h] = q_h @ k_h^T   (6 batched NT, K=64)
    gemm128_kernel<<<dim3(8, 8, 6), 256>>>(OFF_QKV, nullptr, OFF_QKV + 384, nullptr, OFF_QK,
        64, 1152, 1152, 1024, 64, 64, 1048576, 1.0f, 8);

    ta_kernel<<<6144, 256>>>();
    xdiag_kernel<<<1024, 384>>>();

    // q2 = SCALE * x_diag @ q2_w
    gemm64_kernel<<<dim3(6, 8, 1), 256>>>(OFF_XD, q2_w, 0, nullptr, 0, OFF_Q2,
        1024, 384, 384, 384, 384, 384, 0, 0, 0, 0, SCALE, 0, 1, 1);

    int wout = (out_size >= 3145728) ? 1 : 0;

    // stage 2 in 3 groups of 2 heads (Lg overlays dead QK + LG regions)
    for (int g = 0; g < 3; g++) {
        // Lg[hg] = q2_h @ VWall[:, h*64:+64]^T  (2 batched NT, 1024x6144x64)
        gemm128_kernel<<<dim3(48, 8, 2), 256>>>(OFF_Q2 + g * 128, nullptr, OFF_VW + g * 128,
            nullptr, OFF_QK,
            64, 384, 768, 6144, 64, 64, LG_STRIDE, 1.0f, 8);

        middle_kernel<<<dim3(1024, 2), 256>>>(g, out + 1572864, wout);

        // o partials = AB @ VWall[:, 384+h*64:+64]  (2 batched NN, split-K 12)
        gemm64_kernel<<<dim3(1, 8, 24), 256>>>(OFF_QK, nullptr, OFF_VW + 384 + g * 128,
            nullptr, 0, OFF_OPART,
            1024, 64, 6144, 6144, 768, 64, 0, LG_STRIDE, 64, 65536, 1.0f, 0, 2, 12);

        oreduce_kernel<<<512, 256>>>(g);
    }

    // h1 = tok + (o @ proj_w + proj_b)
    gemm64_kernel<<<dim3(6, 8, 1), 256>>>(OFF_O, proj_w, 0, proj_b, OFF_TOK, OFF_H1,
        1024, 384, 384, 384, 384, 384, 384, 0, 0, 0, 1.0f, 1 | 2, 1, 1);

    ln_kernel<<<1024, 384>>>(OFF_H1, ln2_g, ln2_b, OFF_HN);

    // mlp
    gemm128_kernel<<<dim3(12, 8, 1), 256>>>(OFF_HN, fc1_w, 0, fc1_b, OFF_MLP,
        384, 384, 1536, 1536, 0, 0, 0, 1.0f, 1 | 4);
    gemm64_kernel<<<dim3(6, 8, 1), 256>>>(OFF_MLP, fc2_w, 0, fc2_b, OFF_H1, OFF_H2,
        1024, 384, 1536, 1536, 384, 384, 384, 0, 0, 0, 1.0f, 1 | 2, 1, 1);

    upsample_kernel<<<1536, 256>>>(out, out_size);
}

// round 6
// speedup vs baseline: 1.1730x; 1.0512x over previous
#include <cuda_runtime.h>
#include <math.h>

// ---------------------------------------------------------------------------
// DeformationTrajectoryAttentionBlock — fp32; stage-2 GEMM-ified; f32x2 FMA.
// B=1, F=4, H=6, D=384, G=16, S=256, N=1024, HD=64, IMG=32, MLP_HID=1536
// ---------------------------------------------------------------------------

#define SCALE 0.125f
#define LN_EPS 1e-5f

#define OFF_TOK    0LL          // 1024*384
#define OFF_XN     393216LL
#define OFF_QKV    786432LL     // 1024*1152
#define OFF_VW     1966080LL    // 6*1024*768 (6144 x 768)
#define OFF_QK     6684672LL    // 6*1024*1024 ; reused as Lg[hg=0] after ta
#define OFF_TA     12976128LL   // 1024*256*24
#define OFF_XD     19267584LL
#define OFF_Q2     19660800LL
#define OFF_LG     20054016LL   // 1024*6144 ; Lg[hg=1]
#define LG_STRIDE  13369344LL   // OFF_LG - OFF_QK
#define OFF_OPART  26345472LL   // 24 * 1024*64
#define OFF_O      27918336LL
#define OFF_H1     28311552LL
#define OFF_HN     28704768LL
#define OFF_MLP    29097984LL   // 1024*1536
#define OFF_H2     30670848LL
#define SCRATCH_FLOATS 31064064LL

static __device__ float g_scratch[SCRATCH_FLOATS];

// ---- packed f32x2 helpers --------------------------------------------------
__device__ __forceinline__ unsigned long long pack2b(float x)
{
    unsigned long long r;
    asm("mov.b64 %0, {%1, %1};" : "=l"(r) : "f"(x));
    return r;
}
__device__ __forceinline__ void fma2(unsigned long long& acc,
                                     unsigned long long a, unsigned long long b)
{
    asm("fma.rn.f32x2 %0, %1, %2, %0;" : "+l"(acc) : "l"(a), "l"(b));
}
__device__ __forceinline__ void unpack2(unsigned long long v, float& x, float& y)
{
    asm("mov.b64 {%0, %1}, %2;" : "=f"(x), "=f"(y) : "l"(v));
}

// ---------------------------------------------------------------------------
__global__ void pool_kernel(const float* __restrict__ x)
{
    float* tok = g_scratch + OFF_TOK;
    int fd = blockIdx.x;
    int f = fd / 384;
    const float* xp = x + (size_t)fd * 1024;
    int t = threadIdx.x;
    int gy = t >> 4, gx = t & 15;
    const float* p = xp + (gy * 2) * 32 + gx * 2;
    float m = fmaxf(fmaxf(p[0], p[1]), fmaxf(p[32], p[33]));
    tok[(size_t)(f * 256 + t) * 384 + (fd % 384)] = m;
}

// ---------------------------------------------------------------------------
__global__ void ln_kernel(long long inOff, const float* __restrict__ g,
                          const float* __restrict__ b, long long outOff)
{
    const float* in = g_scratch + inOff;
    float* out = g_scratch + outOff;
    int n = blockIdx.x, t = threadIdx.x;
    float x = in[(size_t)n * 384 + t];
    __shared__ float red[12];
    __shared__ float mv[2];
    float s = x;
    #pragma unroll
    for (int o = 16; o; o >>= 1) s += __shfl_xor_sync(0xffffffffu, s, o);
    if ((t & 31) == 0) red[t >> 5] = s;
    __syncthreads();
    if (t == 0) { float tt = 0.f; for (int i = 0; i < 12; i++) tt += red[i]; mv[0] = tt * (1.0f / 384.0f); }
    __syncthreads();
    float mean = mv[0];
    float d = x - mean;
    s = d * d;
    #pragma unroll
    for (int o = 16; o; o >>= 1) s += __shfl_xor_sync(0xffffffffu, s, o);
    if ((t & 31) == 0) red[t >> 5] = s;
    __syncthreads();
    if (t == 0) { float tt = 0.f; for (int i = 0; i < 12; i++) tt += red[i]; mv[1] = rsqrtf(tt * (1.0f / 384.0f) + LN_EPS); }
    __syncthreads();
    out[(size_t)n * 384 + t] = d * mv[1] * g[t] + b[t];
}

// ---------------------------------------------------------------------------
// gemm128: 128x128x16 tiles, 256 threads, 8x8 microtile (f32x2), dbl-buffered.
// flags: 1=bias 4=gelu 8=NT.
// ---------------------------------------------------------------------------
__global__ void __launch_bounds__(256, 2) gemm128_kernel(
    long long aOff, const float* __restrict__ Bp, long long bOff,
    const float* __restrict__ bias, long long cOff,
    int K, int lda, int ldb, int ldc,
    long long sA, long long sB, long long sC,
    float alpha, int flags)
{
    int z = blockIdx.z;
    const float* A = g_scratch + aOff + (long long)z * sA;
    const float* B = (Bp ? Bp : g_scratch + bOff) + (long long)z * sB;
    float* C = g_scratch + cOff + (long long)z * sC;

    __shared__ __align__(16) float As[2][16][128];
    __shared__ __align__(16) float Bs[2][16][128];

    int bm = blockIdx.y * 128, bn = blockIdx.x * 128;
    int tid = threadIdx.x;
    int r2 = tid >> 1, k8 = (tid & 1) * 8;
    int bk = tid >> 4, c8 = (tid & 15) * 8;
    int ty = tid >> 4, tx = tid & 15;

    int nt = K / 16;
    float4 ar0, ar1, br0, br1;

    {
        const float* ap = A + (long long)(bm + r2) * lda + k8;
        ar0 = *(const float4*)ap; ar1 = *(const float4*)(ap + 4);
        As[0][k8 + 0][r2] = ar0.x; As[0][k8 + 1][r2] = ar0.y;
        As[0][k8 + 2][r2] = ar0.z; As[0][k8 + 3][r2] = ar0.w;
        As[0][k8 + 4][r2] = ar1.x; As[0][k8 + 5][r2] = ar1.y;
        As[0][k8 + 6][r2] = ar1.z; As[0][k8 + 7][r2] = ar1.w;
        if (flags & 8) {
            const float* bp = B + (long long)(bn + r2) * ldb + k8;
            br0 = *(const float4*)bp; br1 = *(const float4*)(bp + 4);
            Bs[0][k8 + 0][r2] = br0.x; Bs[0][k8 + 1][r2] = br0.y;
            Bs[0][k8 + 2][r2] = br0.z; Bs[0][k8 + 3][r2] = br0.w;
            Bs[0][k8 + 4][r2] = br1.x; Bs[0][k8 + 5][r2] = br1.y;
            Bs[0][k8 + 6][r2] = br1.z; Bs[0][k8 + 7][r2] = br1.w;
        } else {
            const float* bp = B + (long long)bk * ldb + bn + c8;
            br0 = *(const float4*)bp; br1 = *(const float4*)(bp + 4);
            *(float4*)&Bs[0][bk][c8] = br0;
            *(float4*)&Bs[0][bk][c8 + 4] = br1;
        }
    }
    __syncthreads();

    unsigned long long acc2[8][4];
    #pragma unroll
    for (int i = 0; i < 8; i++)
        #pragma unroll
        for (int j = 0; j < 4; j++) acc2[i][j] = 0ULL;

    for (int kt = 0; kt < nt; kt++) {
        int cur = kt & 1;
        bool pf = (kt + 1 < nt);
        if (pf) {
            int k0 = (kt + 1) * 16;
            const float* ap = A + (long long)(bm + r2) * lda + k0 + k8;
            ar0 = *(const float4*)ap; ar1 = *(const float4*)(ap + 4);
            if (flags & 8) {
                const float* bp = B + (long long)(bn + r2) * ldb + k0 + k8;
                br0 = *(const float4*)bp; br1 = *(const float4*)(bp + 4);
            } else {
                const float* bp = B + (long long)(k0 + bk) * ldb + bn + c8;
                br0 = *(const float4*)bp; br1 = *(const float4*)(bp + 4);
            }
        }
        #pragma unroll
        for (int kk = 0; kk < 16; kk++) {
            float a[8];
            *(float4*)&a[0] = *(const float4*)&As[cur][kk][ty * 8];
            *(float4*)&a[4] = *(const float4*)&As[cur][kk][ty * 8 + 4];
            const unsigned long long* bsp =
                (const unsigned long long*)&Bs[cur][kk][tx * 8];
            unsigned long long b0 = bsp[0], b1 = bsp[1], b2 = bsp[2], b3 = bsp[3];
            #pragma unroll
            for (int i = 0; i < 8; i++) {
                unsigned long long pa = pack2b(a[i]);
                fma2(acc2[i][0], pa, b0);
                fma2(acc2[i][1], pa, b1);
                fma2(acc2[i][2], pa, b2);
                fma2(acc2[i][3], pa, b3);
            }
        }
        if (pf) {
            int nx = 1 - cur;
            As[nx][k8 + 0][r2] = ar0.x; As[nx][k8 + 1][r2] = ar0.y;
            As[nx][k8 + 2][r2] = ar0.z; As[nx][k8 + 3][r2] = ar0.w;
            As[nx][k8 + 4][r2] = ar1.x; As[nx][k8 + 5][r2] = ar1.y;
            As[nx][k8 + 6][r2] = ar1.z; As[nx][k8 + 7][r2] = ar1.w;
            if (flags & 8) {
                Bs[nx][k8 + 0][r2] = br0.x; Bs[nx][k8 + 1][r2] = br0.y;
                Bs[nx][k8 + 2][r2] = br0.z; Bs[nx][k8 + 3][r2] = br0.w;
                Bs[nx][k8 + 4][r2] = br1.x; Bs[nx][k8 + 5][r2] = br1.y;
                Bs[nx][k8 + 6][r2] = br1.z; Bs[nx][k8 + 7][r2] = br1.w;
            } else {
                *(float4*)&Bs[nx][bk][c8] = br0;
                *(float4*)&Bs[nx][bk][c8 + 4] = br1;
            }
            __syncthreads();
        }
    }

    int row0 = bm + ty * 8, col0 = bn + tx * 8;
    #pragma unroll
    for (int i = 0; i < 8; i++) {
        float v[8];
        #pragma unroll
        for (int j = 0; j < 4; j++)
            unpack2(acc2[i][j], v[2 * j], v[2 * j + 1]);
        #pragma unroll
        for (int j = 0; j < 8; j++) {
            float t = alpha * v[j];
            if (flags & 1) t += bias[col0 + j];
            if (flags & 4) t = 0.5f * t * (1.0f + erff(t * 0.7071067811865476f));
            v[j] = t;
        }
        float* cp = C + (long long)(row0 + i) * ldc + col0;
        *(float4*)cp = *(float4*)&v[0];
        *(float4*)(cp + 4) = *(float4*)&v[4];
    }
}

// ---------------------------------------------------------------------------
// gemm64: 128x64x16 tiles, 8x4 microtile (f32x2), dbl-buffered.
// flags: 1=bias 2=residual 4=gelu 8=NT. z: zb=z%nB batch, zk=z/nB K-split.
// ---------------------------------------------------------------------------
__global__ void __launch_bounds__(256) gemm64_kernel(
    long long aOff, const float* __restrict__ Bp, long long bOff,
    const float* __restrict__ bias, long long rOff, long long cOff,
    int M, int N, int K, int lda, int ldb, int ldc, int ldr,
    long long sA, long long sB, long long sC,
    float alpha, int flags, int nB, int ksplit)
{
    int z = blockIdx.z;
    int zb = z % nB, zk = z / nB;
    int Kloc = K / ksplit;
    const float* A = g_scratch + aOff + (long long)zb * sA + (long long)zk * Kloc;
    const float* Bb = (Bp ? Bp : g_scratch + bOff) + (long long)zb * sB;
    const float* B = Bb + ((flags & 8) ? (long long)zk * Kloc
                                       : (long long)zk * Kloc * ldb);
    float* C = g_scratch + cOff + (long long)z * sC;

    __shared__ __align__(16) float As[2][16][128];
    __shared__ __align__(16) float Bs[2][16][64];

    int bm = blockIdx.y * 128, bn = blockIdx.x * 64;
    int tid = threadIdx.x;
    int a_r = tid >> 1, a_k = (tid & 1) * 8;
    int tx = tid & 15, ty = tid >> 4;

    int nt = Kloc / 16;
    float4 ar0, ar1, br0;

    {
        const float* ap = A + (long long)(bm + a_r) * lda + a_k;
        ar0 = *(const float4*)ap; ar1 = *(const float4*)(ap + 4);
        As[0][a_k + 0][a_r] = ar0.x; As[0][a_k + 1][a_r] = ar0.y;
        As[0][a_k + 2][a_r] = ar0.z; As[0][a_k + 3][a_r] = ar0.w;
        As[0][a_k + 4][a_r] = ar1.x; As[0][a_k + 5][a_r] = ar1.y;
        As[0][a_k + 6][a_r] = ar1.z; As[0][a_k + 7][a_r] = ar1.w;
        if (flags & 8) {
            int r = tid >> 2, k4 = (tid & 3) * 4;
            br0 = *(const float4*)(B + (long long)(bn + r) * ldb + k4);
            Bs[0][k4 + 0][r] = br0.x; Bs[0][k4 + 1][r] = br0.y;
            Bs[0][k4 + 2][r] = br0.z; Bs[0][k4 + 3][r] = br0.w;
        } else {
            int kk = tid >> 4, n4 = (tid & 15) * 4;
            br0 = *(const float4*)(B + (long long)kk * ldb + bn + n4);
            *(float4*)&Bs[0][kk][n4] = br0;
        }
    }
    __syncthreads();

    unsigned long long acc2[8][2];
    #pragma unroll
    for (int i = 0; i < 8; i++) { acc2[i][0] = 0ULL; acc2[i][1] = 0ULL; }

    for (int kt = 0; kt < nt; kt++) {
        int cur = kt & 1;
        bool pf = (kt + 1 < nt);
        if (pf) {
            int k0 = (kt + 1) * 16;
            const float* ap = A + (long long)(bm + a_r) * lda + k0 + a_k;
            ar0 = *(const float4*)ap; ar1 = *(const float4*)(ap + 4);
            if (flags & 8) {
                int r = tid >> 2, k4 = (tid & 3) * 4;
                br0 = *(const float4*)(B + (long long)(bn + r) * ldb + k0 + k4);
            } else {
                int kk = tid >> 4, n4 = (tid & 15) * 4;
                br0 = *(const float4*)(B + (long long)(k0 + kk) * ldb + bn + n4);
            }
        }
        #pragma unroll
        for (int kk = 0; kk < 16; kk++) {
            float a[8];
            *(float4*)&a[0] = *(const float4*)&As[cur][kk][ty * 8];
            *(float4*)&a[4] = *(const float4*)&As[cur][kk][ty * 8 + 4];
            const unsigned long long* bsp =
                (const unsigned long long*)&Bs[cur][kk][tx * 4];
            unsigned long long b0 = bsp[0], b1 = bsp[1];
            #pragma unroll
            for (int i = 0; i < 8; i++) {
                unsigned long long pa = pack2b(a[i]);
                fma2(acc2[i][0], pa, b0);
                fma2(acc2[i][1], pa, b1);
            }
        }
        if (pf) {
            int nx = 1 - cur;
            As[nx][a_k + 0][a_r] = ar0.x; As[nx][a_k + 1][a_r] = ar0.y;
            As[nx][a_k + 2][a_r] = ar0.z; As[nx][a_k + 3][a_r] = ar0.w;
            As[nx][a_k + 4][a_r] = ar1.x; As[nx][a_k + 5][a_r] = ar1.y;
            As[nx][a_k + 6][a_r] = ar1.z; As[nx][a_k + 7][a_r] = ar1.w;
            if (flags & 8) {
                int r = tid >> 2, k4 = (tid & 3) * 4;
                Bs[nx][k4 + 0][r] = br0.x; Bs[nx][k4 + 1][r] = br0.y;
                Bs[nx][k4 + 2][r] = br0.z; Bs[nx][k4 + 3][r] = br0.w;
            } else {
                int kk = tid >> 4, n4 = (tid & 15) * 4;
                *(float4*)&Bs[nx][kk][n4] = br0;
            }
            __syncthreads();
        }
    }

    int row0 = bm + ty * 8, col0 = bn + tx * 4;
    const float* R = g_scratch + rOff;
    #pragma unroll
    for (int i = 0; i < 8; i++) {
        float v[4];
        unpack2(acc2[i][0], v[0], v[1]);
        unpack2(acc2[i][1], v[2], v[3]);
        #pragma unroll
        for (int j = 0; j < 4; j++) {
            float t = alpha * v[j];
            if (flags & 1) t += bias[col0 + j];
            if (flags & 4) t = 0.5f * t * (1.0f + erff(t * 0.7071067811865476f));
            if (flags & 2) t += R[(long long)(row0 + i) * ldr + col0 + j];
            C[(long long)(row0 + i) * ldc + col0 + j] = t;
        }
    }
}

// ---------------------------------------------------------------------------
__global__ void ta_kernel()
{
    const float* qk = g_scratch + OFF_QK;
    float* ta = g_scratch + OFF_TA;
    int b = blockIdx.x;
    int h = b >> 10, n = b & 1023;
    int s = threadIdx.x;
    const float* p = qk + ((size_t)b << 10) + s;
    float x0 = SCALE * p[0], x1 = SCALE * p[256], x2 = SCALE * p[512], x3 = SCALE * p[768];
    float m = fmaxf(fmaxf(x0, x1), fmaxf(x2, x3));
    float e0 = expf(x0 - m), e1 = expf(x1 - m), e2 = expf(x2 - m), e3 = expf(x3 - m);
    float inv = 1.0f / (e0 + e1 + e2 + e3);
    float* o = ta + ((size_t)(n * 256 + s)) * 24 + h * 4;
    o[0] = e0 * inv; o[1] = e1 * inv; o[2] = e2 * inv; o[3] = e3 * inv;
}

// ---------------------------------------------------------------------------
__global__ void xdiag_kernel()
{
    const float* ta = g_scratch + OFF_TA;
    const float* qkv = g_scratch + OFF_QKV;
    float* xd = g_scratch + OFF_XD;
    int n = blockIdx.x, c = threadIdx.x;
    int h = c >> 6;
    int s = n & 255;
    const float* tp = ta + ((size_t)(n * 256 + s)) * 24 + h * 4;
    float acc = 0.f;
    #pragma unroll
    for (int f = 0; f < 4; f++)
        acc += tp[f] * qkv[(size_t)(f * 256 + s) * 1152 + 768 + c];
    xd[(size_t)n * 384 + c] = acc;
}

// ---------------------------------------------------------------------------
// middle (head group g, hg = blockIdx.y): logits + softmax + AB in place
// ---------------------------------------------------------------------------
__global__ void __launch_bounds__(256) middle_kernel(int g, float* __restrict__ out_attn,
                                                     int write_out)
{
    int n = blockIdx.x;
    int hg = blockIdx.y;
    int s = threadIdx.x;
    __shared__ __align__(16) float sta[256][24];
    __shared__ float red[8];
    __shared__ float mv[2];

    const float4* tap = (const float4*)(g_scratch + OFF_TA + (size_t)n * 6144);
    float4* stp = (float4*)&sta[0][0];
    for (int idx = s; idx < 1536; idx += 256)
        stp[idx] = tap[idx];
    __syncthreads();

    float* lg = g_scratch + OFF_QK + (long long)hg * LG_STRIDE + (size_t)n * 6144;
    float logit = 0.f;
    #pragma unroll
    for (int j = 0; j < 24; j++)
        logit += sta[s][j] * lg[j * 256 + s];

    float m = logit;
    #pragma unroll
    for (int o = 16; o; o >>= 1) m = fmaxf(m, __shfl_xor_sync(0xffffffffu, m, o));
    if ((s & 31) == 0) red[s >> 5] = m;
    __syncthreads();
    if (s == 0) { float t = red[0]; for (int i = 1; i < 8; i++) t = fmaxf(t, red[i]); mv[0] = t; }
    __syncthreads();
    float e = expf(logit - mv[0]);
    float sum = e;
    #pragma unroll
    for (int o = 16; o; o >>= 1) sum += __shfl_xor_sync(0xffffffffu, sum, o);
    if ((s & 31) == 0) red[s >> 5] = sum;
    __syncthreads();
    if (s == 0) { float t = 0.f; for (int i = 0; i < 8; i++) t += red[i]; mv[1] = 1.0f / t; }
    __syncthreads();
    float sa = e * mv[1];
    if (write_out) out_attn[((size_t)(g * 2 + hg) * 1024 + n) * 256 + s] = sa;
    #pragma unroll
    for (int j = 0; j < 24; j++)
        lg[j * 256 + s] = sa * sta[s][j];
}

// ---------------------------------------------------------------------------
__global__ void oreduce_kernel(int g)
{
    const float* opart = g_scratch + OFF_OPART;
    float* o = g_scratch + OFF_O;
    int i = blockIdx.x * 256 + threadIdx.x;       // < 131072
    int hg = i >> 16;
    int r = i & 65535;
    float sum = 0.f;
    #pragma unroll
    for (int zk = 0; zk < 12; zk++)
        sum += opart[(size_t)(zk * 2 + hg) * 65536 + r];
    o[(size_t)(r >> 6) * 384 + (g * 2 + hg) * 64 + (r & 63)] = sum;
}

// ---------------------------------------------------------------------------
__global__ void upsample_kernel(float* __restrict__ out, int out_size)
{
    const float* h2 = g_scratch + OFF_H2;
    int fd = blockIdx.x;
    int f = fd / 384, d = fd % 384;
    __shared__ float ch[256];
    int t = threadIdx.x;
    ch[t] = h2[(size_t)(f * 256 + t) * 384 + d];
    __syncthreads();
    #pragma unroll
    for (int p = 0; p < 4; p++) {
        int o = t + p * 256;
        int oy = o >> 5, ox = o & 31;
        float fy = 0.5f * oy - 0.25f;
        int iy0 = (int)floorf(fy);
        float wy = fy - (float)iy0;
        int iy0c = max(iy0, 0), iy1c = min(iy0 + 1, 15);
        float fx = 0.5f * ox - 0.25f;
        int ix0 = (int)floorf(fx);
        float wx = fx - (float)ix0;
        int ix0c = max(ix0, 0), ix1c = min(ix0 + 1, 15);
        float v00 = ch[iy0c * 16 + ix0c], v01 = ch[iy0c * 16 + ix1c];
        float v10 = ch[iy1c * 16 + ix0c], v11 = ch[iy1c * 16 + ix1c];
        float v = (1.f - wy) * ((1.f - wx) * v00 + wx * v01)
                + wy * ((1.f - wx) * v10 + wx * v11);
        long long oi = (long long)fd * 1024 + o;
        if (oi < (long long)out_size) out[oi] = v;
    }
}

// ---------------------------------------------------------------------------
extern "C" void kernel_launch(void* const* d_in, const int* in_sizes, int n_in,
                              void* d_out, int out_size)
{
    (void)in_sizes; (void)n_in;
    const float* x      = (const float*)d_in[0];
    const float* qkv_w  = (const float*)d_in[1];
    const float* q2_w   = (const float*)d_in[2];
    const float* kv2_w  = (const float*)d_in[3];
    const float* proj_w = (const float*)d_in[4];
    const float* proj_b = (const float*)d_in[5];
    const float* ln1_g  = (const float*)d_in[6];
    const float* ln1_b  = (const float*)d_in[7];
    const float* ln2_g  = (const float*)d_in[8];
    const float* ln2_b  = (const float*)d_in[9];
    const float* fc1_w  = (const float*)d_in[10];
    const float* fc1_b  = (const float*)d_in[11];
    const float* fc2_w  = (const float*)d_in[12];
    const float* fc2_b  = (const float*)d_in[13];
    float* out = (float*)d_out;

    pool_kernel<<<1536, 256>>>(x);
    ln_kernel<<<1024, 384>>>(OFF_TOK, ln1_g, ln1_b, OFF_XN);

    // qkv = xn @ qkv_w   (1024 x 1152 x 384, NN)
    gemm128_kernel<<<dim3(9, 8, 1), 256>>>(OFF_XN, qkv_w, 0, nullptr, OFF_QKV,
        384, 384, 1152, 1152, 0, 0, 0, 1.0f, 0);

    // VW[h'] = v_h' @ kv2_w[h' slice]   (6 batched NN, K=64)
    gemm128_kernel<<<dim3(6, 8, 6), 256>>>(OFF_QKV + 768, kv2_w, 0, nullptr, OFF_VW,
        64, 1152, 768, 768, 64, 49152, 786432, 1.0f, 0);

    // qk[h] = q_h @ k_h^T   (6 batched NT, K=64)
    gemm128_kernel<<<dim3(8, 8, 6), 256>>>(OFF_QKV, nullptr, OFF_QKV + 384, nullptr, OFF_QK,
        64, 1152, 1152, 1024, 64, 64, 1048576, 1.0f, 8);

    ta_kernel<<<6144, 256>>>();
    xdiag_kernel<<<1024, 384>>>();

    // q2 = SCALE * x_diag @ q2_w
    gemm64_kernel<<<dim3(6, 8, 1), 256>>>(OFF_XD, q2_w, 0, nullptr, 0, OFF_Q2,
        1024, 384, 384, 384, 384, 384, 0, 0, 0, 0, SCALE, 0, 1, 1);

    int wout = (out_size >= 3145728) ? 1 : 0;

    // stage 2 in 3 groups of 2 heads (Lg overlays dead QK + LG regions)
    for (int g = 0; g < 3; g++) {
        // Lg[hg] = q2_h @ VWall[:, h*64:+64]^T  (2 batched NT, 1024x6144x64)
        gemm128_kernel<<<dim3(48, 8, 2), 256>>>(OFF_Q2 + g * 128, nullptr, OFF_VW + g * 128,
            nullptr, OFF_QK,
            64, 384, 768, 6144, 64, 64, LG_STRIDE, 1.0f, 8);

        middle_kernel<<<dim3(1024, 2), 256>>>(g, out + 1572864, wout);

        // o partials = AB @ VWall[:, 384+h*64:+64]  (2 batched NN, split-K 12)
        gemm64_kernel<<<dim3(1, 8, 24), 256>>>(OFF_QK, nullptr, OFF_VW + 384 + g * 128,
            nullptr, 0, OFF_OPART,
            1024, 64, 6144, 6144, 768, 64, 0, LG_STRIDE, 64, 65536, 1.0f, 0, 2, 12);

        oreduce_kernel<<<512, 256>>>(g);
    }

    // h1 = tok + (o @ proj_w + proj_b)
    gemm64_kernel<<<dim3(6, 8, 1), 256>>>(OFF_O, proj_w, 0, proj_b, OFF_TOK, OFF_H1,
        1024, 384, 384, 384, 384, 384, 384, 0, 0, 0, 1.0f, 1 | 2, 1, 1);

    ln_kernel<<<1024, 384>>>(OFF_H1, ln2_g, ln2_b, OFF_HN);

    // mlp
    gemm128_kernel<<<dim3(12, 8, 1), 256>>>(OFF_HN, fc1_w, 0, fc1_b, OFF_MLP,
        384, 384, 1536, 1536, 0, 0, 0, 1.0f, 1 | 4);
    gemm64_kernel<<<dim3(6, 8, 1), 256>>>(OFF_MLP, fc2_w, 0, fc2_b, OFF_H1, OFF_H2,
        1024, 384, 1536, 1536, 384, 384, 384, 0, 0, 0, 1.0f, 1 | 2, 1, 1);

    upsample_kernel<<<1536, 256>>>(out, out_size);
}